// round 8
// baseline (speedup 1.0000x reference)
#include <cuda_runtime.h>
#include <cuda_fp16.h>
#include <math.h>
#include <stdint.h>

// ---------------- problem constants ----------------
#define B_ 512
#define D_ 512
#define C_ 100000

#define S_F    30.0f
#define COSM_F 0.8775825618903728f
#define SINM_F 0.479425538604203f
#define TH_F  (-0.8775825618903728f)
#define MM_F   0.2397127693021015f

// ---------------- device scratch ----------------
__device__ __half g_Xh[B_ * D_];
__device__ __half g_Wh[(size_t)C_ * D_];
__device__ int g_label[B_];

// ---------------- helpers ----------------
__device__ __forceinline__ uint32_t smem_u32(const void* p) {
    uint32_t a;
    asm("{ .reg .u64 t; cvta.to.shared.u64 t, %1; cvt.u32.u64 %0, t; }" : "=r"(a) : "l"(p));
    return a;
}

#define CP16(sm, gp, sz) \
    asm volatile("cp.async.cg.shared.global [%0], [%1], 16, %2;" \
                 :: "r"(sm), "l"(gp), "r"(sz) : "memory")

#define LDSM4(r, addr) \
    asm volatile("ldmatrix.sync.aligned.m8n8.x4.shared.b16 {%0,%1,%2,%3}, [%4];" \
                 : "=r"((r)[0]), "=r"((r)[1]), "=r"((r)[2]), "=r"((r)[3]) : "r"(addr))

#define MMA(acc, a, b) \
    asm volatile("mma.sync.aligned.m16n8k16.row.col.f32.f16.f16.f32 " \
                 "{%0,%1,%2,%3},{%4,%5,%6,%7},{%8,%9},{%0,%1,%2,%3};" \
                 : "+f"((acc)[0]), "+f"((acc)[1]), "+f"((acc)[2]), "+f"((acc)[3]) \
                 : "r"((a)[0]), "r"((a)[1]), "r"((a)[2]), "r"((a)[3]), \
                   "r"((b)[0]), "r"((b)[1]))

__device__ __forceinline__ uint32_t h2u(__half2 h) {
    return *reinterpret_cast<uint32_t*>(&h);
}

__device__ __forceinline__ float arcf(float c, bool isl) {
    c = fminf(1.0f, fmaxf(-1.0f, c));
    float s2 = fminf(1.0f, fmaxf(1e-9f, 1.0f - c * c));
    float sn;
    asm("sqrt.approx.f32 %0, %1;" : "=f"(sn) : "f"(s2));
    float phi = c * COSM_F - sn * SINM_F;
    phi = (c > TH_F) ? phi : (c - MM_F);
    return (isl ? phi : c) * S_F;
}

// ---------------- unified prep: normalize W and X to fp16, decode labels ----
// Blocks [0, 50000): W rows 2b, 2b+1.  Blocks [50000, 50256): X rows + labels.
#define WBLKS (C_ / 2)
__global__ __launch_bounds__(256)
void prep_kernel(const float* __restrict__ X, const float* __restrict__ W,
                 const int* __restrict__ raw) {
    int b = blockIdx.x;
    int h = threadIdx.x >> 7;          // 0/1: which row of this block
    int t = threadIdx.x & 127;         // 128 threads per row
    int row;
    const float* src;
    __half* dst;
    if (b < WBLKS) {
        row = b * 2 + h;
        src = W + (size_t)row * D_;
        dst = g_Wh + (size_t)row * D_;
    } else {
        row = (b - WBLKS) * 2 + h;
        src = X + (size_t)row * D_;
        dst = g_Xh + (size_t)row * D_;
    }
    const float4* sf = reinterpret_cast<const float4*>(src);
    float4 v = sf[t];
    float s = v.x * v.x + v.y * v.y + v.z * v.z + v.w * v.w;
#pragma unroll
    for (int o = 16; o > 0; o >>= 1) s += __shfl_xor_sync(0xffffffffu, s, o);
    __shared__ float ws[8];
    if ((t & 31) == 0) ws[h * 4 + (t >> 5)] = s;
    __syncthreads();
    float tot = ws[h * 4 + 0] + ws[h * 4 + 1] + ws[h * 4 + 2] + ws[h * 4 + 3];
    float inv = 1.0f / fmaxf(sqrtf(tot), 1e-12f);
    uint2 hv;
    hv.x = h2u(__floats2half2_rn(v.x * inv, v.y * inv));
    hv.y = h2u(__floats2half2_rn(v.z * inv, v.w * inv));
    *reinterpret_cast<uint2*>(dst + t * 4) = hv;

    // label decode (X blocks only, one lane per row). int64 layout iff the
    // first 8 odd int32 words are all zero (labels < 100000 guarantee it;
    // p(false positive) for 8 random int32 ~ 2^-256).
    if (b >= WBLKS && t == 0) {
        int odd = raw[1] | raw[3] | raw[5] | raw[7] | raw[9] | raw[11] | raw[13] | raw[15];
        g_label[row] = (odd == 0) ? raw[2 * row] : raw[row];
    }
}

// ---------------- GEMM + ArcFace (single-product fp16 mma.sync) -----------
// CTA 128x128, BK=64 fp16 (128B rows, SW128 swizzle), 3-stage cp.async,
// round-4 schedule (measured best), 2 CTAs/SM.
#define A_OFF 0
#define B_OFF 16384
#define STAGE_SZ 32768
#define NSTAGE 3
#define SMEM_TOTAL (NSTAGE * STAGE_SZ)   // 98304

__global__ __launch_bounds__(256, 2)
void arcface_mma_kernel(float* __restrict__ out) {
    extern __shared__ char Smem[];
    __shared__ int slab[128];
    const uint32_t sb = smem_u32(Smem);
    const int tid = threadIdx.x;
    const int lane = tid & 31;
    const int wid = tid >> 5;
    const int m0 = blockIdx.x * 128;   // x fastest -> 4 m-tiles share W n-tile in L2
    // reversed n order: freshest g_Wh lines (written last by prep) are read first
    const int n0 = ((int)gridDim.y - 1 - (int)blockIdx.y) * 128;
    const int mW = (wid >> 2) * 64;    // warp tile 64x32
    const int nW = (wid & 3) * 32;

    if (tid < 128) slab[tid] = g_label[m0 + tid];

    float acc[4][4][4];
#pragma unroll
    for (int i = 0; i < 4; i++)
#pragma unroll
        for (int j = 0; j < 4; j++)
#pragma unroll
            for (int q = 0; q < 4; q++) acc[i][j][q] = 0.0f;

    // ldmatrix lane-address components
    const int arow = mW + (lane & 7) + ((lane >> 3) & 1) * 8;   // + 16*i
    const int acol = ((lane >> 4) & 1) * 16;                    // + 32*g
    const int brow = nW + ((lane >> 4) & 1) * 8 + (lane & 7);   // + 16*jp
    const int bcol = ((lane >> 3) & 1) * 16;
    const int sx   = (lane & 7) * 16;                           // swizzle xor

    auto load_stage = [&](int kc, int st) {
        uint32_t base = sb + st * STAGE_SZ;
#pragma unroll
        for (int j = 0; j < 4; j++) {
            int idx = tid + 256 * j;
            int r = idx >> 3, c = idx & 7;
            uint32_t doff = (uint32_t)(r * 128 + ((c * 16) ^ ((r & 7) * 16)));
            size_t abyt = (size_t)(m0 + r) * (D_ * 2) + kc * 128 + c * 16;
            CP16(base + A_OFF + doff, (const char*)g_Xh + abyt, 16);
            int n = n0 + r;
            int ok = (n < C_) ? 16 : 0;
            int nn = (n < C_) ? n : 0;
            size_t bbyt = (size_t)nn * (D_ * 2) + kc * 128 + c * 16;
            CP16(base + B_OFF + doff, (const char*)g_Wh + bbyt, ok);
        }
    };

    auto compute_stage = [&](int st) {
        const uint32_t Ab = sb + st * STAGE_SZ + A_OFF;
        const uint32_t Bb = sb + st * STAGE_SZ + B_OFF;
#pragma unroll
        for (int g = 0; g < 4; g++) {
            uint32_t bh[4][2];
#pragma unroll
            for (int jp = 0; jp < 2; jp++) {
                uint32_t boff = (uint32_t)((brow + 16 * jp) * 128 + ((g * 32 + bcol) ^ sx));
                uint32_t t4[4];
                LDSM4(t4, Bb + boff);
                bh[2 * jp][0] = t4[0]; bh[2 * jp][1] = t4[1];
                bh[2 * jp + 1][0] = t4[2]; bh[2 * jp + 1][1] = t4[3];
            }
#pragma unroll
            for (int i = 0; i < 4; i++) {
                uint32_t a4[4];
                uint32_t aoff = (uint32_t)((arow + 16 * i) * 128 + ((g * 32 + acol) ^ sx));
                LDSM4(a4, Ab + aoff);
#pragma unroll
                for (int j = 0; j < 4; j++) MMA(acc[i][j], a4, bh[j]);
            }
        }
    };

    // ---- prologue: fill stages 0..2 ----
    load_stage(0, 0);
    asm volatile("cp.async.commit_group;" ::: "memory");
    load_stage(1, 1);
    asm volatile("cp.async.commit_group;" ::: "memory");
    load_stage(2, 2);
    asm volatile("cp.async.commit_group;" ::: "memory");

    // ---- main loop (round-4 schedule, fully unrolled) ----
#pragma unroll
    for (int kc = 0; kc < 8; kc++) {
        asm volatile("cp.async.wait_group 2;" ::: "memory");
        __syncthreads();
        compute_stage(kc % 3);
        __syncthreads();
        if (kc + 3 < 8) load_stage(kc + 3, kc % 3);
        asm volatile("cp.async.commit_group;" ::: "memory");
    }

    // ---- epilogue: ArcFace + direct stores ----
#pragma unroll
    for (int i = 0; i < 4; i++) {
        int lm = mW + i * 16 + (lane >> 2);
        int gm = m0 + lm;
        int lab0 = slab[lm];
        int lab1 = slab[lm + 8];
#pragma unroll
        for (int j = 0; j < 4; j++) {
            int col = n0 + nW + j * 8 + (lane & 3) * 2;
            if (col < C_) {   // C_ even -> pair stays in-bounds together
                float2 v0, v1;
                v0.x = arcf(acc[i][j][0], col == lab0);
                v0.y = arcf(acc[i][j][1], col + 1 == lab0);
                v1.x = arcf(acc[i][j][2], col == lab1);
                v1.y = arcf(acc[i][j][3], col + 1 == lab1);
                *reinterpret_cast<float2*>(out + (size_t)gm * C_ + col) = v0;
                *reinterpret_cast<float2*>(out + (size_t)(gm + 8) * C_ + col) = v1;
            }
        }
    }
}

// ---------------- launch ----------------
extern "C" void kernel_launch(void* const* d_in, const int* in_sizes, int n_in,
                              void* d_out, int out_size) {
    const float* X = nullptr;
    const float* W = nullptr;
    const void*  L = nullptr;

    for (int i = 0; i < n_in; i++) {
        int s = in_sizes[i];
        if (s == B_ * D_)      X = (const float*)d_in[i];
        else if (s == C_ * D_) W = (const float*)d_in[i];
        else if (s == B_)      L = d_in[i];
    }
    if (!X) X = (const float*)d_in[0];
    if (!L) L = d_in[1];
    if (!W) W = (const float*)d_in[2];

    float* out = (float*)d_out;

    prep_kernel<<<WBLKS + B_ / 2, 256>>>(X, W, (const int*)L);

    cudaFuncSetAttribute(arcface_mma_kernel,
                         cudaFuncAttributeMaxDynamicSharedMemorySize, SMEM_TOTAL);
    dim3 grid(4, (C_ + 127) / 128);   // x = m-tile (fast) for W L2 reuse
    arcface_mma_kernel<<<grid, 256, SMEM_TOTAL>>>(out);
    (void)out_size;
}

// round 9
// speedup vs baseline: 1.1051x; 1.1051x over previous
#include <cuda_runtime.h>
#include <cuda_fp16.h>
#include <math.h>
#include <stdint.h>

// ---------------- problem constants ----------------
#define B_ 512
#define D_ 512
#define C_ 100000

#define S_F    30.0f
#define COSM_F 0.8775825618903728f
#define SINM_F 0.479425538604203f
#define TH_F  (-0.8775825618903728f)
#define MM_F   0.2397127693021015f

// ---------------- device scratch ----------------
__device__ __half g_Xh[B_ * D_];
__device__ int g_label[B_];

// ---------------- helpers ----------------
__device__ __forceinline__ uint32_t smem_u32(const void* p) {
    uint32_t a;
    asm("{ .reg .u64 t; cvta.to.shared.u64 t, %1; cvt.u32.u64 %0, t; }" : "=r"(a) : "l"(p));
    return a;
}

#define CP16(sm, gp) \
    asm volatile("cp.async.cg.shared.global [%0], [%1], 16;" \
                 :: "r"(sm), "l"(gp) : "memory")

#define LDSM4(r, addr) \
    asm volatile("ldmatrix.sync.aligned.m8n8.x4.shared.b16 {%0,%1,%2,%3}, [%4];" \
                 : "=r"((r)[0]), "=r"((r)[1]), "=r"((r)[2]), "=r"((r)[3]) : "r"(addr))

#define MMA(acc, a, b) \
    asm volatile("mma.sync.aligned.m16n8k16.row.col.f32.f16.f16.f32 " \
                 "{%0,%1,%2,%3},{%4,%5,%6,%7},{%8,%9},{%0,%1,%2,%3};" \
                 : "+f"((acc)[0]), "+f"((acc)[1]), "+f"((acc)[2]), "+f"((acc)[3]) \
                 : "r"((a)[0]), "r"((a)[1]), "r"((a)[2]), "r"((a)[3]), \
                   "r"((b)[0]), "r"((b)[1]))

__device__ __forceinline__ uint32_t h2u(__half2 h) {
    return *reinterpret_cast<uint32_t*>(&h);
}

__device__ __forceinline__ float arcf(float c, bool isl) {
    c = fminf(1.0f, fmaxf(-1.0f, c));
    float s2 = fminf(1.0f, fmaxf(1e-9f, 1.0f - c * c));
    float sn;
    asm("sqrt.approx.f32 %0, %1;" : "=f"(sn) : "f"(s2));
    float phi = c * COSM_F - sn * SINM_F;
    phi = (c > TH_F) ? phi : (c - MM_F);
    return (isl ? phi : c) * S_F;
}

// ---------------- X: normalize + fp16 convert + label decode ----------------
__global__ void xprep_kernel(const float* __restrict__ X, const int* __restrict__ raw) {
    int row = blockIdx.x;
    int t = threadIdx.x;  // 128
    const float4* xf = reinterpret_cast<const float4*>(X + (size_t)row * D_);
    float4 v = xf[t];
    float s = v.x * v.x + v.y * v.y + v.z * v.z + v.w * v.w;
#pragma unroll
    for (int o = 16; o > 0; o >>= 1) s += __shfl_xor_sync(0xffffffffu, s, o);
    __shared__ float ws[4];
    if ((t & 31) == 0) ws[t >> 5] = s;
    __syncthreads();
    float tot = ws[0] + ws[1] + ws[2] + ws[3];
    float inv = 1.0f / fmaxf(sqrtf(tot), 1e-12f);
    uint2 hv;
    hv.x = h2u(__floats2half2_rn(v.x * inv, v.y * inv));
    hv.y = h2u(__floats2half2_rn(v.z * inv, v.w * inv));
    *reinterpret_cast<uint2*>(g_Xh + (size_t)row * D_ + t * 4) = hv;

    // label decode: int64 layout iff first 8 odd int32 words are all zero
    if (t == 0) {
        int odd = raw[1] | raw[3] | raw[5] | raw[7] | raw[9] | raw[11] | raw[13] | raw[15];
        g_label[row] = (odd == 0) ? raw[2 * row] : raw[row];
    }
}

// ---------------- persistent-W GEMM + ArcFace ----------------
// One CTA per n-tile (128 rows of W). Phase 1: convert W fp32 -> fp16 into
// 128KB resident smem (+ row norms). Phase 2: loop 4 m-tiles, stream A via
// 3-stage cp.async, 64 MMAs/warp per (m,k)-chunk. 256 threads, 1 CTA/SM.
#define B_RES_SZ   131072                  // 8 chunks x 16KB
#define A_ST_OFF   131072
#define A_STAGE_SZ 16384
#define SMEM_TOTAL (B_RES_SZ + 3 * A_STAGE_SZ)   // 180224

__global__ __launch_bounds__(256, 1)
void arcface_wres_kernel(const float* __restrict__ W, float* __restrict__ out) {
    extern __shared__ char Smem[];
    __shared__ float invs[128];
    const uint32_t sb = smem_u32(Smem);
    const uint32_t sbA = sb + A_ST_OFF;
    const int tid = threadIdx.x;
    const int lane = tid & 31;
    const int wid = tid >> 5;
    const int n0 = blockIdx.x * 128;
    const int mW = (wid >> 2) * 64;    // warp tile 64x32
    const int nW = (wid & 3) * 32;

    // producer mapping: idx = tid + 256*j -> row r = idx>>3, chunk c = idx&7
    const int pr = tid >> 3;   // 0..31 (+32*j)
    const int pc = tid & 7;

    // ---- A prefetch for chunks 0,1 (overlaps W conversion) ----
    auto loadA = [&](int it, int st) {
        int mt = it >> 3, kc = it & 7;
        uint32_t base = sbA + st * A_STAGE_SZ;
#pragma unroll
        for (int j = 0; j < 4; j++) {
            int r = pr + 32 * j;
            uint32_t doff = (uint32_t)(r * 128 + ((pc * 16) ^ ((r & 7) * 16)));
            size_t abyt = (size_t)(mt * 128 + r) * (D_ * 2) + kc * 128 + pc * 16;
            CP16(base + doff, (const char*)g_Xh + abyt);
        }
    };

    loadA(0, 0);
    asm volatile("cp.async.commit_group;" ::: "memory");
    loadA(1, 1);
    asm volatile("cp.async.commit_group;" ::: "memory");

    // ---- phase 1: W fp32 -> fp16 resident smem + row sumsq ----
    float ssq[4] = {0.f, 0.f, 0.f, 0.f};
    for (int kc = 0; kc < 8; kc++) {
        char* chk = Smem + kc * 16384;
#pragma unroll
        for (int j = 0; j < 4; j++) {
            int r = pr + 32 * j;
            int n = n0 + r;
            float4 f0, f1;
            if (n < C_) {
                const float4* p = reinterpret_cast<const float4*>(
                    W + (size_t)n * D_ + kc * 64 + pc * 8);
                f0 = p[0];
                f1 = p[1];
            } else {
                f0 = make_float4(0.f, 0.f, 0.f, 0.f);
                f1 = f0;
            }
            ssq[j] += f0.x * f0.x + f0.y * f0.y + f0.z * f0.z + f0.w * f0.w
                    + f1.x * f1.x + f1.y * f1.y + f1.z * f1.z + f1.w * f1.w;
            uint4 hv;
            hv.x = h2u(__floats2half2_rn(f0.x, f0.y));
            hv.y = h2u(__floats2half2_rn(f0.z, f0.w));
            hv.z = h2u(__floats2half2_rn(f1.x, f1.y));
            hv.w = h2u(__floats2half2_rn(f1.z, f1.w));
            uint32_t doff = (uint32_t)(r * 128 + ((pc * 16) ^ ((r & 7) * 16)));
            *reinterpret_cast<uint4*>(chk + doff) = hv;
        }
    }
#pragma unroll
    for (int j = 0; j < 4; j++) {
        float s = ssq[j];
        s += __shfl_xor_sync(0xffffffffu, s, 1);
        s += __shfl_xor_sync(0xffffffffu, s, 2);
        s += __shfl_xor_sync(0xffffffffu, s, 4);
        if (pc == 0) invs[pr + 32 * j] = 1.0f / fmaxf(sqrtf(s), 1e-12f);
    }

    // ldmatrix lane-address components
    const int arow = mW + (lane & 7) + ((lane >> 3) & 1) * 8;   // + 16*i
    const int acol = ((lane >> 4) & 1) * 16;                    // + 32*g
    const int brow = nW + ((lane >> 4) & 1) * 8 + (lane & 7);   // + 16*jp
    const int bcol = ((lane >> 3) & 1) * 16;
    const int sx   = (lane & 7) * 16;                           // swizzle xor

    float acc[4][4][4];
#pragma unroll
    for (int i = 0; i < 4; i++)
#pragma unroll
        for (int j = 0; j < 4; j++)
#pragma unroll
            for (int q = 0; q < 4; q++) acc[i][j][q] = 0.0f;

    // ---- phase 2: 32 linear (m,k) chunks, single barrier per iter ----
    int stC = 0;   // compute stage = it % 3
    for (int it = 0; it < 32; it++) {
        asm volatile("cp.async.wait_group 1;" ::: "memory");
        __syncthreads();
        if (it + 2 < 32) {
            int stL = stC + 2 >= 3 ? stC - 1 : stC + 2;
            loadA(it + 2, stL);
        }
        asm volatile("cp.async.commit_group;" ::: "memory");

        const uint32_t Ab = sbA + stC * A_STAGE_SZ;
        const uint32_t Bb = sb + (it & 7) * 16384;
#pragma unroll
        for (int g = 0; g < 4; g++) {
            uint32_t bh[4][2];
#pragma unroll
            for (int jp = 0; jp < 2; jp++) {
                uint32_t boff = (uint32_t)((brow + 16 * jp) * 128 + ((g * 32 + bcol) ^ sx));
                uint32_t t4[4];
                LDSM4(t4, Bb + boff);
                bh[2 * jp][0] = t4[0]; bh[2 * jp][1] = t4[1];
                bh[2 * jp + 1][0] = t4[2]; bh[2 * jp + 1][1] = t4[3];
            }
#pragma unroll
            for (int i = 0; i < 4; i++) {
                uint32_t a4[4];
                uint32_t aoff = (uint32_t)((arow + 16 * i) * 128 + ((g * 32 + acol) ^ sx));
                LDSM4(a4, Ab + aoff);
#pragma unroll
                for (int j = 0; j < 4; j++) MMA(acc[i][j], a4, bh[j]);
            }
        }
        if (++stC == 3) stC = 0;

        // ---- per-m-tile epilogue ----
        if ((it & 7) == 7) {
            int mt = it >> 3;
#pragma unroll
            for (int i = 0; i < 4; i++) {
                int lm = mW + i * 16 + (lane >> 2);
                int gm = mt * 128 + lm;
                int lab0 = g_label[gm];
                int lab1 = g_label[gm + 8];
#pragma unroll
                for (int j = 0; j < 4; j++) {
                    int colL = nW + j * 8 + (lane & 3) * 2;
                    int col = n0 + colL;
                    if (col < C_) {   // C_ even -> pair in-bounds together
                        float i0 = invs[colL], i1 = invs[colL + 1];
                        float2 v0, v1;
                        v0.x = arcf(acc[i][j][0] * i0, col == lab0);
                        v0.y = arcf(acc[i][j][1] * i1, col + 1 == lab0);
                        v1.x = arcf(acc[i][j][2] * i0, col == lab1);
                        v1.y = arcf(acc[i][j][3] * i1, col + 1 == lab1);
                        *reinterpret_cast<float2*>(out + (size_t)gm * C_ + col) = v0;
                        *reinterpret_cast<float2*>(out + (size_t)(gm + 8) * C_ + col) = v1;
                    }
#pragma unroll
                    for (int q = 0; q < 4; q++) acc[i][j][q] = 0.0f;
                }
            }
        }
    }
}

// ---------------- launch ----------------
extern "C" void kernel_launch(void* const* d_in, const int* in_sizes, int n_in,
                              void* d_out, int out_size) {
    const float* X = nullptr;
    const float* W = nullptr;
    const void*  L = nullptr;

    for (int i = 0; i < n_in; i++) {
        int s = in_sizes[i];
        if (s == B_ * D_)      X = (const float*)d_in[i];
        else if (s == C_ * D_) W = (const float*)d_in[i];
        else if (s == B_)      L = d_in[i];
    }
    if (!X) X = (const float*)d_in[0];
    if (!L) L = d_in[1];
    if (!W) W = (const float*)d_in[2];

    float* out = (float*)d_out;

    xprep_kernel<<<B_, 128>>>(X, (const int*)L);

    cudaFuncSetAttribute(arcface_wres_kernel,
                         cudaFuncAttributeMaxDynamicSharedMemorySize, SMEM_TOTAL);
    arcface_wres_kernel<<<(C_ + 127) / 128, 256, SMEM_TOTAL>>>(W, out);
    (void)out_size;
}

// round 10
// speedup vs baseline: 1.2898x; 1.1671x over previous
#include <cuda_runtime.h>
#include <cuda_fp16.h>
#include <math.h>
#include <stdint.h>

// ---------------- problem constants ----------------
#define B_ 512
#define D_ 512
#define C_ 100000

#define S_F    30.0f
#define COSM_F 0.8775825618903728f
#define SINM_F 0.479425538604203f
#define TH_F  (-0.8775825618903728f)
#define MM_F   0.2397127693021015f

// ---------------- device scratch ----------------
__device__ __half g_Xh[B_ * D_];
__device__ __half g_Wh[(size_t)C_ * D_];
__device__ int g_label[B_];

// ---------------- helpers ----------------
__device__ __forceinline__ uint32_t smem_u32(const void* p) {
    uint32_t a;
    asm("{ .reg .u64 t; cvta.to.shared.u64 t, %1; cvt.u32.u64 %0, t; }" : "=r"(a) : "l"(p));
    return a;
}

#define CP16(sm, gp, sz) \
    asm volatile("cp.async.cg.shared.global [%0], [%1], 16, %2;" \
                 :: "r"(sm), "l"(gp), "r"(sz) : "memory")

#define LDSM4(r, addr) \
    asm volatile("ldmatrix.sync.aligned.m8n8.x4.shared.b16 {%0,%1,%2,%3}, [%4];" \
                 : "=r"((r)[0]), "=r"((r)[1]), "=r"((r)[2]), "=r"((r)[3]) : "r"(addr))

#define MMA(acc, a, b) \
    asm volatile("mma.sync.aligned.m16n8k16.row.col.f32.f16.f16.f32 " \
                 "{%0,%1,%2,%3},{%4,%5,%6,%7},{%8,%9},{%0,%1,%2,%3};" \
                 : "+f"((acc)[0]), "+f"((acc)[1]), "+f"((acc)[2]), "+f"((acc)[3]) \
                 : "r"((a)[0]), "r"((a)[1]), "r"((a)[2]), "r"((a)[3]), \
                   "r"((b)[0]), "r"((b)[1]))

__device__ __forceinline__ uint32_t h2u(__half2 h) {
    return *reinterpret_cast<uint32_t*>(&h);
}

__device__ __forceinline__ float arcf(float c, bool isl) {
    c = fminf(1.0f, fmaxf(-1.0f, c));
    float s2 = fminf(1.0f, fmaxf(1e-9f, 1.0f - c * c));
    float sn;
    asm("sqrt.approx.f32 %0, %1;" : "=f"(sn) : "f"(s2));
    float phi = c * COSM_F - sn * SINM_F;
    phi = (c > TH_F) ? phi : (c - MM_F);
    return (isl ? phi : c) * S_F;
}

// ---------------- X: normalize + fp16 convert + label decode ----------------
__global__ void xprep_kernel(const float* __restrict__ X, const int* __restrict__ raw) {
    int row = blockIdx.x;
    int t = threadIdx.x;  // 128
    const float4* xf = reinterpret_cast<const float4*>(X + (size_t)row * D_);
    float4 v = xf[t];
    float s = v.x * v.x + v.y * v.y + v.z * v.z + v.w * v.w;
#pragma unroll
    for (int o = 16; o > 0; o >>= 1) s += __shfl_xor_sync(0xffffffffu, s, o);
    __shared__ float ws[4];
    if ((t & 31) == 0) ws[t >> 5] = s;
    __syncthreads();
    float tot = ws[0] + ws[1] + ws[2] + ws[3];
    float inv = 1.0f / fmaxf(sqrtf(tot), 1e-12f);
    uint2 hv;
    hv.x = h2u(__floats2half2_rn(v.x * inv, v.y * inv));
    hv.y = h2u(__floats2half2_rn(v.z * inv, v.w * inv));
    *reinterpret_cast<uint2*>(g_Xh + (size_t)row * D_ + t * 4) = hv;

    if (t == 0) {
        int odd = raw[1] | raw[3] | raw[5] | raw[7] | raw[9] | raw[11] | raw[13] | raw[15];
        g_label[row] = (odd == 0) ? raw[2 * row] : raw[row];
    }
}

// ---------------- W: normalize + fp16 convert (2 rows per block) ----------
__global__ __launch_bounds__(256)
void wprep_kernel(const float* __restrict__ W) {
    int h = threadIdx.x >> 7;
    int t = threadIdx.x & 127;
    int row = blockIdx.x * 2 + h;      // C_ even -> always valid
    const float4* wf = reinterpret_cast<const float4*>(W + (size_t)row * D_);
    float4 v = wf[t];
    float s = v.x * v.x + v.y * v.y + v.z * v.z + v.w * v.w;
#pragma unroll
    for (int o = 16; o > 0; o >>= 1) s += __shfl_xor_sync(0xffffffffu, s, o);
    __shared__ float ws[8];
    if ((t & 31) == 0) ws[h * 4 + (t >> 5)] = s;
    __syncthreads();
    float tot = ws[h * 4 + 0] + ws[h * 4 + 1] + ws[h * 4 + 2] + ws[h * 4 + 3];
    float inv = 1.0f / fmaxf(sqrtf(tot), 1e-12f);
    uint2 hv;
    hv.x = h2u(__floats2half2_rn(v.x * inv, v.y * inv));
    hv.y = h2u(__floats2half2_rn(v.z * inv, v.w * inv));
    *reinterpret_cast<uint2*>(g_Wh + (size_t)row * D_ + t * 4) = hv;
}

// ---------------- GEMM + ArcFace: 64x128 CTA tile, 3 CTAs/SM ------------
// BK=64 fp16 (128B rows, SW128 swizzle), 3-stage cp.async, 256 threads,
// 8 warps as 2(m) x 4(n), warp tile 32x32.
#define A_OFF 0
#define B_OFF 8192
#define STAGE_SZ 24576
#define SMEM_TOTAL (3 * STAGE_SZ)   // 73728 -> 3 CTAs/SM (221KB)

__global__ __launch_bounds__(256, 3)
void arcface_mma_kernel(float* __restrict__ out) {
    extern __shared__ char Smem[];
    __shared__ int slab[64];
    const uint32_t sb = smem_u32(Smem);
    const int tid = threadIdx.x;
    const int lane = tid & 31;
    const int wid = tid >> 5;
    const int m0 = blockIdx.x * 64;    // x fastest -> 8 m-tiles share W n-tile in L2
    const int n0 = blockIdx.y * 128;
    const int mW = (wid >> 2) * 32;    // warp tile 32x32
    const int nW = (wid & 3) * 32;

    if (tid < 64) slab[tid] = g_label[m0 + tid];

    float acc[2][4][4];
#pragma unroll
    for (int i = 0; i < 2; i++)
#pragma unroll
        for (int j = 0; j < 4; j++)
#pragma unroll
            for (int q = 0; q < 4; q++) acc[i][j][q] = 0.0f;

    // ldmatrix lane-address components
    const int arow = mW + (lane & 7) + ((lane >> 3) & 1) * 8;   // + 16*i
    const int acol = ((lane >> 4) & 1) * 16;                    // + 32*g
    const int brow = nW + ((lane >> 4) & 1) * 8 + (lane & 7);   // + 16*jp
    const int bcol = ((lane >> 3) & 1) * 16;
    const int sx   = (lane & 7) * 16;                           // swizzle xor

    // producer: A 64 rows (2 iters of 256 chunk-slots), B 128 rows (4 iters)
    auto load_stage = [&](int kc, int st) {
        uint32_t base = sb + st * STAGE_SZ;
        int r0 = tid >> 3, c = tid & 7;
        uint32_t dc = (uint32_t)(c * 16);
#pragma unroll
        for (int j = 0; j < 2; j++) {
            int r = r0 + 32 * j;
            uint32_t doff = (uint32_t)(r * 128 + (dc ^ ((r & 7) * 16)));
            size_t abyt = (size_t)(m0 + r) * (D_ * 2) + kc * 128 + c * 16;
            CP16(base + A_OFF + doff, (const char*)g_Xh + abyt, 16);
        }
#pragma unroll
        for (int j = 0; j < 4; j++) {
            int r = r0 + 32 * j;
            uint32_t doff = (uint32_t)(r * 128 + (dc ^ ((r & 7) * 16)));
            int n = n0 + r;
            int ok = (n < C_) ? 16 : 0;
            int nn = (n < C_) ? n : 0;
            size_t bbyt = (size_t)nn * (D_ * 2) + kc * 128 + c * 16;
            CP16(base + B_OFF + doff, (const char*)g_Wh + bbyt, ok);
        }
    };

    auto compute_stage = [&](int st) {
        const uint32_t Ab = sb + st * STAGE_SZ + A_OFF;
        const uint32_t Bb = sb + st * STAGE_SZ + B_OFF;
#pragma unroll
        for (int g = 0; g < 4; g++) {
            uint32_t bh[4][2];
#pragma unroll
            for (int jp = 0; jp < 2; jp++) {
                uint32_t boff = (uint32_t)((brow + 16 * jp) * 128 + ((g * 32 + bcol) ^ sx));
                uint32_t t4[4];
                LDSM4(t4, Bb + boff);
                bh[2 * jp][0] = t4[0]; bh[2 * jp][1] = t4[1];
                bh[2 * jp + 1][0] = t4[2]; bh[2 * jp + 1][1] = t4[3];
            }
#pragma unroll
            for (int i = 0; i < 2; i++) {
                uint32_t a4[4];
                uint32_t aoff = (uint32_t)((arow + 16 * i) * 128 + ((g * 32 + acol) ^ sx));
                LDSM4(a4, Ab + aoff);
#pragma unroll
                for (int j = 0; j < 4; j++) MMA(acc[i][j], a4, bh[j]);
            }
        }
    };

    // ---- prologue: fill stages 0..2 ----
    load_stage(0, 0);
    asm volatile("cp.async.commit_group;" ::: "memory");
    load_stage(1, 1);
    asm volatile("cp.async.commit_group;" ::: "memory");
    load_stage(2, 2);
    asm volatile("cp.async.commit_group;" ::: "memory");

    // ---- main loop (R4-validated schedule) ----
    for (int kc = 0; kc < 8; kc++) {
        asm volatile("cp.async.wait_group 2;" ::: "memory");
        __syncthreads();
        compute_stage(kc % 3);
        __syncthreads();
        if (kc + 3 < 8) load_stage(kc + 3, kc % 3);
        asm volatile("cp.async.commit_group;" ::: "memory");
    }

    // ---- epilogue: ArcFace + direct stores ----
#pragma unroll
    for (int i = 0; i < 2; i++) {
        int lm = mW + i * 16 + (lane >> 2);
        int gm = m0 + lm;
        int lab0 = slab[lm];
        int lab1 = slab[lm + 8];
#pragma unroll
        for (int j = 0; j < 4; j++) {
            int col = n0 + nW + j * 8 + (lane & 3) * 2;
            if (col < C_) {   // C_ even -> pair stays in-bounds together
                float2 v0, v1;
                v0.x = arcf(acc[i][j][0], col == lab0);
                v0.y = arcf(acc[i][j][1], col + 1 == lab0);
                v1.x = arcf(acc[i][j][2], col == lab1);
                v1.y = arcf(acc[i][j][3], col + 1 == lab1);
                *reinterpret_cast<float2*>(out + (size_t)gm * C_ + col) = v0;
                *reinterpret_cast<float2*>(out + (size_t)(gm + 8) * C_ + col) = v1;
            }
        }
    }
}

// ---------------- launch ----------------
extern "C" void kernel_launch(void* const* d_in, const int* in_sizes, int n_in,
                              void* d_out, int out_size) {
    const float* X = nullptr;
    const float* W = nullptr;
    const void*  L = nullptr;

    for (int i = 0; i < n_in; i++) {
        int s = in_sizes[i];
        if (s == B_ * D_)      X = (const float*)d_in[i];
        else if (s == C_ * D_) W = (const float*)d_in[i];
        else if (s == B_)      L = d_in[i];
    }
    if (!X) X = (const float*)d_in[0];
    if (!L) L = d_in[1];
    if (!W) W = (const float*)d_in[2];

    float* out = (float*)d_out;

    xprep_kernel<<<B_, 128>>>(X, (const int*)L);
    wprep_kernel<<<C_ / 2, 256>>>(W);

    cudaFuncSetAttribute(arcface_mma_kernel,
                         cudaFuncAttributeMaxDynamicSharedMemorySize, SMEM_TOTAL);
    dim3 grid(8, (C_ + 127) / 128);   // x = m-tile (fast) for W L2 reuse
    arcface_mma_kernel<<<grid, 256, SMEM_TOTAL>>>(out);
    (void)out_size;
}

// round 11
// speedup vs baseline: 1.3684x; 1.0610x over previous
#include <cuda_runtime.h>
#include <cuda_fp16.h>
#include <math.h>
#include <stdint.h>

// ---------------- problem constants ----------------
#define B_ 512
#define D_ 512
#define C_ 100000

#define S_F    30.0f
#define COSM_F 0.8775825618903728f
#define SINM_F 0.479425538604203f
#define TH_F  (-0.8775825618903728f)
#define MM_F   0.2397127693021015f

// ---------------- device scratch ----------------
__device__ __half g_Xh[B_ * D_];
__device__ __half g_Wh[(size_t)C_ * D_];
__device__ int g_label[B_];

// ---------------- helpers ----------------
__device__ __forceinline__ uint32_t smem_u32(const void* p) {
    uint32_t a;
    asm("{ .reg .u64 t; cvta.to.shared.u64 t, %1; cvt.u32.u64 %0, t; }" : "=r"(a) : "l"(p));
    return a;
}

#define CP16(sm, gp, sz) \
    asm volatile("cp.async.cg.shared.global [%0], [%1], 16, %2;" \
                 :: "r"(sm), "l"(gp), "r"(sz) : "memory")

#define LDSM4(r, addr) \
    asm volatile("ldmatrix.sync.aligned.m8n8.x4.shared.b16 {%0,%1,%2,%3}, [%4];" \
                 : "=r"((r)[0]), "=r"((r)[1]), "=r"((r)[2]), "=r"((r)[3]) : "r"(addr))

#define MMA(acc, a, b) \
    asm volatile("mma.sync.aligned.m16n8k16.row.col.f32.f16.f16.f32 " \
                 "{%0,%1,%2,%3},{%4,%5,%6,%7},{%8,%9},{%0,%1,%2,%3};" \
                 : "+f"((acc)[0]), "+f"((acc)[1]), "+f"((acc)[2]), "+f"((acc)[3]) \
                 : "r"((a)[0]), "r"((a)[1]), "r"((a)[2]), "r"((a)[3]), \
                   "r"((b)[0]), "r"((b)[1]))

#define STG2_CS(ptr, vx, vy) \
    asm volatile("st.global.cs.v2.f32 [%0], {%1, %2};" \
                 :: "l"(ptr), "f"(vx), "f"(vy) : "memory")

__device__ __forceinline__ uint32_t h2u(__half2 h) {
    return *reinterpret_cast<uint32_t*>(&h);
}

__device__ __forceinline__ float arcf(float c, bool isl) {
    c = fminf(1.0f, fmaxf(-1.0f, c));
    float s2 = fminf(1.0f, fmaxf(1e-9f, 1.0f - c * c));
    float sn;
    asm("sqrt.approx.f32 %0, %1;" : "=f"(sn) : "f"(s2));
    float phi = c * COSM_F - sn * SINM_F;
    phi = (c > TH_F) ? phi : (c - MM_F);
    return (isl ? phi : c) * S_F;
}

// ---------------- X: normalize + fp16 convert + label decode ----------------
__global__ void xprep_kernel(const float* __restrict__ X, const int* __restrict__ raw) {
    int row = blockIdx.x;
    int t = threadIdx.x;  // 128
    const float4* xf = reinterpret_cast<const float4*>(X + (size_t)row * D_);
    float4 v = xf[t];
    float s = v.x * v.x + v.y * v.y + v.z * v.z + v.w * v.w;
#pragma unroll
    for (int o = 16; o > 0; o >>= 1) s += __shfl_xor_sync(0xffffffffu, s, o);
    __shared__ float ws[4];
    if ((t & 31) == 0) ws[t >> 5] = s;
    __syncthreads();
    float tot = ws[0] + ws[1] + ws[2] + ws[3];
    float inv = 1.0f / fmaxf(sqrtf(tot), 1e-12f);
    uint2 hv;
    hv.x = h2u(__floats2half2_rn(v.x * inv, v.y * inv));
    hv.y = h2u(__floats2half2_rn(v.z * inv, v.w * inv));
    *reinterpret_cast<uint2*>(g_Xh + (size_t)row * D_ + t * 4) = hv;

    // label decode: int64 layout iff first 8 odd int32 words are all zero
    // (labels < 100000 guarantee zero high words; p(false pos) ~ 2^-256)
    if (t == 0) {
        int odd = raw[1] | raw[3] | raw[5] | raw[7] | raw[9] | raw[11] | raw[13] | raw[15];
        g_label[row] = (odd == 0) ? raw[2 * row] : raw[row];
    }
}

// ---------------- W: normalize + fp16 convert (4 rows per 512-thr block) ----
__global__ __launch_bounds__(512)
void wprep_kernel(const float* __restrict__ W) {
    int h = threadIdx.x >> 7;          // 0..3: which row of this block
    int t = threadIdx.x & 127;         // 128 threads per row
    int row = blockIdx.x * 4 + h;      // C_ % 4 == 0 -> always valid
    const float4* wf = reinterpret_cast<const float4*>(W + (size_t)row * D_);
    float4 v = wf[t];
    float s = v.x * v.x + v.y * v.y + v.z * v.z + v.w * v.w;
#pragma unroll
    for (int o = 16; o > 0; o >>= 1) s += __shfl_xor_sync(0xffffffffu, s, o);
    __shared__ float ws[16];
    if ((t & 31) == 0) ws[h * 4 + (t >> 5)] = s;
    __syncthreads();
    float tot = ws[h * 4 + 0] + ws[h * 4 + 1] + ws[h * 4 + 2] + ws[h * 4 + 3];
    float inv = 1.0f / fmaxf(sqrtf(tot), 1e-12f);
    uint2 hv;
    hv.x = h2u(__floats2half2_rn(v.x * inv, v.y * inv));
    hv.y = h2u(__floats2half2_rn(v.z * inv, v.w * inv));
    *reinterpret_cast<uint2*>(g_Wh + (size_t)row * D_ + t * 4) = hv;
}

// ---------------- GEMM + ArcFace (R4 config: 128x128, 2 CTAs/SM) ----------
#define A_OFF 0
#define B_OFF 16384
#define STAGE_SZ 32768
#define NSTAGE 3
#define SMEM_TOTAL (NSTAGE * STAGE_SZ)   // 98304

__global__ __launch_bounds__(256, 2)
void arcface_mma_kernel(float* __restrict__ out) {
    extern __shared__ char Smem[];
    __shared__ int slab[128];
    const uint32_t sb = smem_u32(Smem);
    const int tid = threadIdx.x;
    const int lane = tid & 31;
    const int wid = tid >> 5;
    const int m0 = blockIdx.x * 128;   // x fastest -> 4 m-tiles share W n-tile in L2
    const int n0 = blockIdx.y * 128;
    const int mW = (wid >> 2) * 64;    // warp tile 64x32
    const int nW = (wid & 3) * 32;

    if (tid < 128) slab[tid] = g_label[m0 + tid];

    float acc[4][4][4];
#pragma unroll
    for (int i = 0; i < 4; i++)
#pragma unroll
        for (int j = 0; j < 4; j++)
#pragma unroll
            for (int q = 0; q < 4; q++) acc[i][j][q] = 0.0f;

    // ldmatrix lane-address components
    const int arow = mW + (lane & 7) + ((lane >> 3) & 1) * 8;   // + 16*i
    const int acol = ((lane >> 4) & 1) * 16;                    // + 32*g
    const int brow = nW + ((lane >> 4) & 1) * 8 + (lane & 7);   // + 16*jp
    const int bcol = ((lane >> 3) & 1) * 16;
    const int sx   = (lane & 7) * 16;                           // swizzle xor

    auto load_stage = [&](int kc, int st) {
        uint32_t base = sb + st * STAGE_SZ;
#pragma unroll
        for (int j = 0; j < 4; j++) {
            int idx = tid + 256 * j;
            int r = idx >> 3, c = idx & 7;
            uint32_t doff = (uint32_t)(r * 128 + ((c * 16) ^ ((r & 7) * 16)));
            size_t abyt = (size_t)(m0 + r) * (D_ * 2) + kc * 128 + c * 16;
            CP16(base + A_OFF + doff, (const char*)g_Xh + abyt, 16);
            int n = n0 + r;
            int ok = (n < C_) ? 16 : 0;
            int nn = (n < C_) ? n : 0;
            size_t bbyt = (size_t)nn * (D_ * 2) + kc * 128 + c * 16;
            CP16(base + B_OFF + doff, (const char*)g_Wh + bbyt, ok);
        }
    };

    auto compute_stage = [&](int st) {
        const uint32_t Ab = sb + st * STAGE_SZ + A_OFF;
        const uint32_t Bb = sb + st * STAGE_SZ + B_OFF;
#pragma unroll
        for (int g = 0; g < 4; g++) {
            uint32_t bh[4][2];
#pragma unroll
            for (int jp = 0; jp < 2; jp++) {
                uint32_t boff = (uint32_t)((brow + 16 * jp) * 128 + ((g * 32 + bcol) ^ sx));
                uint32_t t4[4];
                LDSM4(t4, Bb + boff);
                bh[2 * jp][0] = t4[0]; bh[2 * jp][1] = t4[1];
                bh[2 * jp + 1][0] = t4[2]; bh[2 * jp + 1][1] = t4[3];
            }
#pragma unroll
            for (int i = 0; i < 4; i++) {
                uint32_t a4[4];
                uint32_t aoff = (uint32_t)((arow + 16 * i) * 128 + ((g * 32 + acol) ^ sx));
                LDSM4(a4, Ab + aoff);
#pragma unroll
                for (int j = 0; j < 4; j++) MMA(acc[i][j], a4, bh[j]);
            }
        }
    };

    // ---- prologue: fill stages 0..2 ----
    load_stage(0, 0);
    asm volatile("cp.async.commit_group;" ::: "memory");
    load_stage(1, 1);
    asm volatile("cp.async.commit_group;" ::: "memory");
    load_stage(2, 2);
    asm volatile("cp.async.commit_group;" ::: "memory");

    // ---- main loop (R4 schedule, not unrolled) ----
    for (int kc = 0; kc < 8; kc++) {
        asm volatile("cp.async.wait_group 2;" ::: "memory");
        __syncthreads();
        compute_stage(kc % 3);
        __syncthreads();
        if (kc + 3 < 8) load_stage(kc + 3, kc % 3);
        asm volatile("cp.async.commit_group;" ::: "memory");
    }

    // ---- epilogue: ArcFace + streaming stores ----
#pragma unroll
    for (int i = 0; i < 4; i++) {
        int lm = mW + i * 16 + (lane >> 2);
        int gm = m0 + lm;
        int lab0 = slab[lm];
        int lab1 = slab[lm + 8];
#pragma unroll
        for (int j = 0; j < 4; j++) {
            int col = n0 + nW + j * 8 + (lane & 3) * 2;
            if (col < C_) {   // C_ even -> pair stays in-bounds together
                float a0 = arcf(acc[i][j][0], col == lab0);
                float a1 = arcf(acc[i][j][1], col + 1 == lab0);
                float b0 = arcf(acc[i][j][2], col == lab1);
                float b1 = arcf(acc[i][j][3], col + 1 == lab1);
                STG2_CS(out + (size_t)gm * C_ + col, a0, a1);
                STG2_CS(out + (size_t)(gm + 8) * C_ + col, b0, b1);
            }
        }
    }
}

// ---------------- launch ----------------
extern "C" void kernel_launch(void* const* d_in, const int* in_sizes, int n_in,
                              void* d_out, int out_size) {
    const float* X = nullptr;
    const float* W = nullptr;
    const void*  L = nullptr;

    for (int i = 0; i < n_in; i++) {
        int s = in_sizes[i];
        if (s == B_ * D_)      X = (const float*)d_in[i];
        else if (s == C_ * D_) W = (const float*)d_in[i];
        else if (s == B_)      L = d_in[i];
    }
    if (!X) X = (const float*)d_in[0];
    if (!L) L = d_in[1];
    if (!W) W = (const float*)d_in[2];

    float* out = (float*)d_out;

    xprep_kernel<<<B_, 128>>>(X, (const int*)L);
    wprep_kernel<<<C_ / 4, 512>>>(W);

    cudaFuncSetAttribute(arcface_mma_kernel,
                         cudaFuncAttributeMaxDynamicSharedMemorySize, SMEM_TOTAL);
    dim3 grid(4, (C_ + 127) / 128);   // x = m-tile (fast) for W L2 reuse
    arcface_mma_kernel<<<grid, 256, SMEM_TOTAL>>>(out);
    (void)out_size;
}